// round 1
// baseline (speedup 1.0000x reference)
#include <cuda_runtime.h>

#define NIN      2049   // inputs per frame
#define NOUT     1024   // outputs per frame
#define ROWS     8      // frames per CTA
#define THREADS  512

__global__ void __launch_bounds__(THREADS)
logscale_kernel(const float* __restrict__ x,
                const float* __restrict__ frac,
                const float* __restrict__ cubt,
                const float* __restrict__ triw,
                const int*   __restrict__ pair,
                const int*   __restrict__ cubi,
                const int*   __restrict__ tridx,
                float* __restrict__ out,
                int n_rows, int n_lin, int n_cub, int max_w)
{
    extern __shared__ float sx[];              // ROWS * NIN floats (64 KB)

    const int row0 = blockIdx.x * ROWS;
    const int nr   = min(ROWS, n_rows - row0);

    // ---- Stage nr rows of x into shared memory (linear, coalesced) ----
    // row0 is a multiple of ROWS=8; 8*2049 floats is a multiple of 4, so the
    // chunk base is 16B-aligned -> float4 path is safe for full blocks.
    {
        const float* src  = x + (size_t)row0 * NIN;
        const int total   = nr * NIN;
        const int nv      = total >> 2;
        const float4* s4  = (const float4*)src;
        float4* d4        = (float4*)sx;
        for (int i = threadIdx.x; i < nv; i += THREADS) d4[i] = s4[i];
        for (int i = (nv << 2) + threadIdx.x; i < total; i += THREADS) sx[i] = src[i];
    }
    __syncthreads();

    const int n_sum = n_lin + n_cub;
    const float NEG_INF = __int_as_float(0xff800000);

    // ---- Each thread owns output columns o, o+THREADS; applies its index
    //      data (read from global exactly once) to all ROWS rows. ----
    for (int o = threadIdx.x; o < NOUT; o += THREADS) {
        if (o < n_lin) {
            // Linear interpolation: x0 + f*(x1-x0), x1 index = pair[o]+1
            const int   i0 = pair[o];
            const float f  = frac[o];
            #pragma unroll
            for (int r = 0; r < ROWS; r++) {
                if (r < nr) {
                    const float x0 = sx[r * NIN + i0];
                    const float x1 = sx[r * NIN + i0 + 1];
                    out[(size_t)(row0 + r) * NOUT + o] = x0 + f * (x1 - x0);
                }
            }
        } else if (o < n_sum) {
            // Catmull-Rom cubic
            const int   j  = o - n_lin;
            const int   i0 = cubi[j];
            const float t  = cubt[j];
            #pragma unroll
            for (int r = 0; r < ROWS; r++) {
                if (r < nr) {
                    const float* row = sx + r * NIN;
                    const float xm1 = row[i0 - 1];
                    const float x0  = row[i0];
                    const float x1  = row[i0 + 1];
                    const float x2  = row[i0 + 2];
                    const float v = x0 + 0.5f * t * (x1 - xm1
                                  + t * (2.0f * xm1 - 5.0f * x0 + 4.0f * x1 - x2
                                  + t * (3.0f * (x0 - x1) + x2 - xm1)));
                    out[(size_t)(row0 + r) * NOUT + o] = v;
                }
            }
        } else {
            // Triangular filter: max over window of (x[idx] + weight_db).
            // Padded slots carry weight = -inf (idx = 0), branch-free no-op.
            const int j = o - n_sum;
            const int*   ip = tridx + (size_t)j * max_w;
            const float* wp = triw  + (size_t)j * max_w;
            float m[ROWS];
            #pragma unroll
            for (int r = 0; r < ROWS; r++) m[r] = NEG_INF;
            for (int w = 0; w < max_w; w++) {
                const int   idx = ip[w];
                const float wg  = wp[w];
                #pragma unroll
                for (int r = 0; r < ROWS; r++)
                    m[r] = fmaxf(m[r], sx[r * NIN + idx] + wg);
            }
            #pragma unroll
            for (int r = 0; r < ROWS; r++)
                if (r < nr) out[(size_t)(row0 + r) * NOUT + o] = m[r];
        }
    }
}

extern "C" void kernel_launch(void* const* d_in, const int* in_sizes, int n_in,
                              void* d_out, int out_size)
{
    // metadata order (setup_inputs dict order):
    // 0: x (f32), 1: fraction_linear (f32), 2: cubic_t (f32),
    // 3: triangular_weights (f32), 4: linear_pair_idx (i32),
    // 5: cubic_i0 (i32), 6: triangular_idx (i32)
    const float* x     = (const float*)d_in[0];
    const float* frac  = (const float*)d_in[1];
    const float* cubt  = (const float*)d_in[2];
    const float* triw  = (const float*)d_in[3];
    const int*   pair  = (const int*)d_in[4];
    const int*   cubi  = (const int*)d_in[5];
    const int*   tridx = (const int*)d_in[6];
    float* out = (float*)d_out;

    const int n_lin  = in_sizes[1];
    const int n_cub  = in_sizes[2];
    const int n_tri  = NOUT - n_lin - n_cub;
    const int max_w  = (n_tri > 0) ? in_sizes[3] / n_tri : 0;
    const int n_rows = in_sizes[0] / NIN;

    const int smem = ROWS * NIN * sizeof(float);   // 65568 B -> needs opt-in
    cudaFuncSetAttribute(logscale_kernel,
                         cudaFuncAttributeMaxDynamicSharedMemorySize, smem);

    const int grid = (n_rows + ROWS - 1) / ROWS;   // 200 CTAs for 1600 rows
    logscale_kernel<<<grid, THREADS, smem>>>(x, frac, cubt, triw,
                                             pair, cubi, tridx, out,
                                             n_rows, n_lin, n_cub, max_w);
}

// round 3
// speedup vs baseline: 1.4505x; 1.4505x over previous
#include <cuda_runtime.h>

#define NIN      2049   // inputs per frame
#define NOUT     1024   // outputs per frame
#define ROWS     12     // frames per CTA -> grid = ceil(1600/12) = 134 (single wave)
#define THREADS  512

__device__ __forceinline__ void store_row(float* __restrict__ out, int row0, int r,
                                          int nr, int o, float v)
{
    if (r < nr) out[(size_t)(row0 + r) * NOUT + o] = v;
}

__device__ __forceinline__ void do_output(int o,
                const float* __restrict__ sx,
                const float* __restrict__ frac,
                const float* __restrict__ cubt,
                const float* __restrict__ triw,
                const int*   __restrict__ pair,
                const int*   __restrict__ cubi,
                const int*   __restrict__ tridx,
                float* __restrict__ out,
                int row0, int nr, int n_lin, int n_sum, int max_w)
{
    if (o < n_lin) {
        // Linear: x0 + f*(x1-x0), x1 at i0+1
        const int   i0 = pair[o];
        const float f  = frac[o];
        #pragma unroll
        for (int r = 0; r < ROWS; r++) {
            const float x0 = sx[r * NIN + i0];
            const float x1 = sx[r * NIN + i0 + 1];
            store_row(out, row0, r, nr, o, x0 + f * (x1 - x0));
        }
    } else if (o < n_sum) {
        // Catmull-Rom cubic
        const int   j  = o - n_lin;
        const int   i0 = cubi[j];
        const float t  = cubt[j];
        #pragma unroll
        for (int r = 0; r < ROWS; r++) {
            const float* row = sx + r * NIN;
            const float xm1 = row[i0 - 1];
            const float x0  = row[i0];
            const float x1  = row[i0 + 1];
            const float x2  = row[i0 + 2];
            const float v = x0 + 0.5f * t * (x1 - xm1
                          + t * (2.0f * xm1 - 5.0f * x0 + 4.0f * x1 - x2
                          + t * (3.0f * (x0 - x1) + x2 - xm1)));
            store_row(out, row0, r, nr, o, v);
        }
    } else {
        // Triangular filter: indices are CONTIGUOUS (tridx[j][w] = i0 + w for
        // valid w); padded slots carry weight = -inf, so reading sx[i0+w]
        // unconditionally and adding the weight is branch-free correct.
        const int j  = o - n_sum;
        const int i0 = tridx[(size_t)j * max_w];         // first (always valid) entry
        const float* __restrict__ wp = triw + (size_t)j * max_w;
        float m[ROWS];
        #pragma unroll
        for (int r = 0; r < ROWS; r++) m[r] = __int_as_float(0xff800000);
        #pragma unroll 4
        for (int w = 0; w < max_w; w++) {
            const float wg = __ldg(wp + w);
            const float* p = sx + i0 + w;
            #pragma unroll
            for (int r = 0; r < ROWS; r++)
                m[r] = fmaxf(m[r], p[r * NIN] + wg);
        }
        #pragma unroll
        for (int r = 0; r < ROWS; r++)
            store_row(out, row0, r, nr, o, m[r]);
    }
}

__global__ void __launch_bounds__(THREADS)
logscale_kernel(const float* __restrict__ x,
                const float* __restrict__ frac,
                const float* __restrict__ cubt,
                const float* __restrict__ triw,
                const int*   __restrict__ pair,
                const int*   __restrict__ cubi,
                const int*   __restrict__ tridx,
                float* __restrict__ out,
                int n_rows, int n_lin, int n_cub, int max_w)
{
    extern __shared__ float sx[];              // ROWS * NIN floats (96 KB)

    const int row0 = blockIdx.x * ROWS;
    const int nr   = min(ROWS, n_rows - row0);

    // ---- Stage nr rows of x into shared memory (coalesced float4) ----
    // row0 is a multiple of 12; 12*2049 floats is a multiple of 4, so every
    // CTA's chunk base is 16B-aligned. nr in {12, 4} -> nr*NIN % 4 == 0.
    {
        const float* src  = x + (size_t)row0 * NIN;
        const int total   = nr * NIN;
        const int nv      = total >> 2;
        const float4* s4  = (const float4*)src;
        float4* d4        = (float4*)sx;
        for (int i = threadIdx.x; i < nv; i += THREADS) d4[i] = s4[i];
        for (int i = (nv << 2) + threadIdx.x; i < total; i += THREADS) sx[i] = src[i];
    }
    __syncthreads();

    const int n_sum = n_lin + n_cub;

    // Antisymmetric mapping: thread t owns outputs {t, 1023-t}. Work per
    // output grows monotonically with o, so each thread gets one cheap and
    // one expensive column -> warps finish at nearly the same time.
    const int t = threadIdx.x;
    do_output(t,            sx, frac, cubt, triw, pair, cubi, tridx, out,
              row0, nr, n_lin, n_sum, max_w);
    do_output(NOUT - 1 - t, sx, frac, cubt, triw, pair, cubi, tridx, out,
              row0, nr, n_lin, n_sum, max_w);
}

extern "C" void kernel_launch(void* const* d_in, const int* in_sizes, int n_in,
                              void* d_out, int out_size)
{
    const float* x     = (const float*)d_in[0];
    const float* frac  = (const float*)d_in[1];
    const float* cubt  = (const float*)d_in[2];
    const float* triw  = (const float*)d_in[3];
    const int*   pair  = (const int*)d_in[4];
    const int*   cubi  = (const int*)d_in[5];
    const int*   tridx = (const int*)d_in[6];
    float* out = (float*)d_out;

    const int n_lin  = in_sizes[1];
    const int n_cub  = in_sizes[2];
    const int n_tri  = NOUT - n_lin - n_cub;
    const int max_w  = (n_tri > 0) ? in_sizes[3] / n_tri : 0;
    const int n_rows = in_sizes[0] / NIN;

    const int smem = ROWS * NIN * sizeof(float);   // 98352 B -> opt-in
    cudaFuncSetAttribute(logscale_kernel,
                         cudaFuncAttributeMaxDynamicSharedMemorySize, smem);

    const int grid = (n_rows + ROWS - 1) / ROWS;   // 134 CTAs for 1600 rows
    logscale_kernel<<<grid, THREADS, smem>>>(x, frac, cubt, triw,
                                             pair, cubi, tridx, out,
                                             n_rows, n_lin, n_cub, max_w);
}